// round 2
// baseline (speedup 1.0000x reference)
#include <cuda_runtime.h>

#define DIM (1u<<22)
typedef unsigned long long ull;

// Persistent scratch (allowed: __device__ globals, no allocation)
__device__ ull g_bufA[DIM];                 // packed (re,im) amplitudes
__device__ ull g_bufB[DIM];
__device__ __align__(16) ull g_Upk[4*22*8]; // per gate: 8 packed-broadcast consts
__device__ double g_acc[23];                // z[0..21], total at [22]

__device__ __forceinline__ int SWZ(int a){ return a ^ ((a>>4)&15); }

__device__ __forceinline__ ull fma2(ull a, ull b, ull c){
  ull d; asm("fma.rn.f32x2 %0, %1, %2, %3;" : "=l"(d) : "l"(a), "l"(b), "l"(c)); return d;
}
__device__ __forceinline__ ull mul2(ull a, ull b){
  ull d; asm("mul.rn.f32x2 %0, %1, %2;" : "=l"(d) : "l"(a), "l"(b)); return d;
}
__device__ __forceinline__ ull swp(ull a){ return (a>>32)|(a<<32); }
__device__ __forceinline__ ull packf(float lo, float hi){
  return (ull)__float_as_uint(lo) | ((ull)__float_as_uint(hi)<<32);
}

__device__ __forceinline__ float2 cxmul(float2 a, float2 b){
  return make_float2(a.x*b.x - a.y*b.y, a.x*b.y + a.y*b.x);
}

// Apply 2x2 gate on register-bit J over 16 register-resident packed amps.
// Complex update via packed f32x2: res = (u.x,u.x)*a + (-u.y,u.y)*swap(a) + ...
template<int J>
__device__ __forceinline__ void gate16(ull (&r)[16], const ull* __restrict__ Up){
  const ulonglong2 q0 = ((const ulonglong2*)Up)[0];
  const ulonglong2 q1 = ((const ulonglong2*)Up)[1];
  const ulonglong2 q2 = ((const ulonglong2*)Up)[2];
  const ulonglong2 q3 = ((const ulonglong2*)Up)[3];
  const ull c00=q0.x, d00=q0.y, c01=q1.x, d01=q1.y;
  const ull c10=q2.x, d10=q2.y, c11=q3.x, d11=q3.y;
#pragma unroll
  for (int i=0;i<16;i++){
    if ((i & (1<<J)) == 0){
      const int j2 = i | (1<<J);
      const ull a=r[i], b=r[j2], as=swp(a), bs=swp(b);
      r[i]  = fma2(c00,a, fma2(d00,as, fma2(c01,b, mul2(d01,bs))));
      r[j2] = fma2(c10,a, fma2(d10,as, fma2(c11,b, mul2(d11,bs))));
    }
  }
}

// ---------------------------------------------------------------------------
// Prep: zero accumulators, build 88 fused gates U = RZ*RY*RX, packed-broadcast
// ---------------------------------------------------------------------------
__global__ void k_prep(const float* __restrict__ params){
  int i = threadIdx.x;
  if (i < 23) g_acc[i] = 0.0;
  if (i < 88){
    float tx = 0.5f*params[i*3+0];
    float ty = 0.5f*params[i*3+1];
    float tz = 0.5f*params[i*3+2];
    float cx,sx,cy,sy,cz,sz;
    sincosf(tx,&sx,&cx); sincosf(ty,&sy,&cy); sincosf(tz,&sz,&cz);
    // M = RY*RX
    float2 M00 = make_float2( cy*cx,  sy*sx);
    float2 M01 = make_float2(-sy*cx, -cy*sx);
    float2 M10 = make_float2( sy*cx, -cy*sx);
    float2 M11 = make_float2( cy*cx, -sy*sx);
    float2 em = make_float2(cz,-sz), ep = make_float2(cz,sz); // e^{-itz}, e^{+itz}
    float2 U00=cxmul(em,M00), U01=cxmul(em,M01);
    float2 U10=cxmul(ep,M10), U11=cxmul(ep,M11);
    ull* Up = &g_Upk[i*8];
    Up[0]=packf(U00.x,U00.x); Up[1]=packf(-U00.y,U00.y);
    Up[2]=packf(U01.x,U01.x); Up[3]=packf(-U01.y,U01.y);
    Up[4]=packf(U10.x,U10.x); Up[5]=packf(-U10.y,U10.y);
    Up[6]=packf(U11.x,U11.x); Up[7]=packf(-U11.y,U11.y);
  }
}

// ---------------------------------------------------------------------------
// Pass A: gates on global bits 0..11 (qubits 21..10). Tile = 4096 contiguous.
// 256 thr x 16 amps; 3 staging mappings (4 reg bits each), swizzled LDS.
// Layers >= 2 fuse prior layer's CNOT ladder as Gray-code gather in[y^(y>>1)].
// ---------------------------------------------------------------------------
template<bool FIRST>
__global__ void __launch_bounds__(256,4) k_passA(
    const float* __restrict__ sre, const float* __restrict__ sim,
    int layer, int dir)
{
  __shared__ ull sh[4096];
  const int t = threadIdx.x;
  const unsigned base = (unsigned)blockIdx.x << 12;
  const ull* in  = dir ? g_bufB : g_bufA;
  ull*       out = dir ? g_bufA : g_bufB;
  const ull* Ub = &g_Upk[layer*22*8];
  ull r[16];

  if (FIRST){
#pragma unroll
    for (int v=0;v<16;v++){
      unsigned y = base | ((unsigned)v<<8) | (unsigned)t;
      r[v] = packf(sre[y], sim[y]);
    }
  } else {
#pragma unroll
    for (int v=0;v<16;v++){
      unsigned y = base | ((unsigned)v<<8) | (unsigned)t;
      unsigned x = y ^ (y>>1);          // inverse of CNOT-ladder permutation
      r[v] = in[x];
    }
  }
  // stage M0: reg bit j -> global bit 8+j -> qubit 13-j
  gate16<0>(r, Ub + 13*8);
  gate16<1>(r, Ub + 12*8);
  gate16<2>(r, Ub + 11*8);
  gate16<3>(r, Ub + 10*8);
  // exchange M0 -> M1
#pragma unroll
  for (int v=0;v<16;v++) sh[SWZ((v<<8)|t)] = r[v];
  __syncthreads();
#pragma unroll
  for (int v=0;v<16;v++) r[v] = sh[SWZ(((t>>4)<<8)|(v<<4)|(t&15))];
  // stage M1: reg bit j -> global bit 4+j -> qubit 17-j
  gate16<0>(r, Ub + 17*8);
  gate16<1>(r, Ub + 16*8);
  gate16<2>(r, Ub + 15*8);
  gate16<3>(r, Ub + 14*8);
  // exchange M1 -> M2
  __syncthreads();
#pragma unroll
  for (int v=0;v<16;v++) sh[SWZ(((t>>4)<<8)|(v<<4)|(t&15))] = r[v];
  __syncthreads();
#pragma unroll
  for (int v=0;v<16;v++) r[v] = sh[SWZ((t<<4)|v)];
  // stage M2: reg bit j -> global bit j -> qubit 21-j
  gate16<0>(r, Ub + 21*8);
  gate16<1>(r, Ub + 20*8);
  gate16<2>(r, Ub + 19*8);
  gate16<3>(r, Ub + 18*8);
  // exchange M2 -> M0 and coalesced store
  __syncthreads();
#pragma unroll
  for (int v=0;v<16;v++) sh[SWZ((t<<4)|v)] = r[v];
  __syncthreads();
#pragma unroll
  for (int v=0;v<16;v++) r[v] = sh[SWZ((v<<8)|t)];
#pragma unroll
  for (int v=0;v<16;v++) out[base | ((unsigned)v<<8) | (unsigned)t] = r[v];
}

// ---------------------------------------------------------------------------
// Pass B: gates on global bits 12..21 (qubits 9..0). In-place.
// Tile local a (12b) = (c<<2)|v, c = bits 12..21, v = bits 0..1 payload.
// LAST fuses the final CNOT ladder + <Z_q> reduction (no final state store).
// ---------------------------------------------------------------------------
template<bool LAST>
__global__ void __launch_bounds__(256,4) k_passB(int layer, int sel)
{
  __shared__ ull sh[4096];
  __shared__ double sacc[23];
  const int t = threadIdx.x;
  const unsigned blk = blockIdx.x;
  ull* buf = sel ? g_bufA : g_bufB;
  const ull* Ub = &g_Upk[layer*22*8];
  ull r[16];

  if (LAST){
    if (t < 23) sacc[t] = 0.0;
  }

  // load, mapping M0: a=(v<<8)|t -> g = (v<<18)|((t>>2)<<12)|(blk<<2)|(t&3)
  const unsigned gbase0 = ((unsigned)(t>>2)<<12) | (blk<<2) | (unsigned)(t&3);
#pragma unroll
  for (int v=0;v<16;v++) r[v] = buf[gbase0 | ((unsigned)v<<18)];
  // stage M0: reg bit j -> global bit 18+j -> qubit 3-j
  gate16<0>(r, Ub + 3*8);
  gate16<1>(r, Ub + 2*8);
  gate16<2>(r, Ub + 1*8);
  gate16<3>(r, Ub + 0*8);
  // exchange M0 -> M1
#pragma unroll
  for (int v=0;v<16;v++) sh[SWZ((v<<8)|t)] = r[v];
  __syncthreads();
#pragma unroll
  for (int v=0;v<16;v++) r[v] = sh[SWZ(((t>>4)<<8)|(v<<4)|(t&15))];
  // stage M1: reg bit j -> global bit 14+j -> qubit 7-j
  gate16<0>(r, Ub + 7*8);
  gate16<1>(r, Ub + 6*8);
  gate16<2>(r, Ub + 5*8);
  gate16<3>(r, Ub + 4*8);
  // exchange M1 -> M2
  __syncthreads();
#pragma unroll
  for (int v=0;v<16;v++) sh[SWZ(((t>>4)<<8)|(v<<4)|(t&15))] = r[v];
  __syncthreads();
#pragma unroll
  for (int v=0;v<16;v++) r[v] = sh[SWZ((t<<4)|v)];
  // stage M2: reg bits 2,3 -> global bits 12,13 -> qubits 9,8
  gate16<2>(r, Ub + 9*8);
  gate16<3>(r, Ub + 8*8);

  if (!LAST){
    // exchange M2 -> M0 and in-place coalesced store
    __syncthreads();
#pragma unroll
    for (int v=0;v<16;v++) sh[SWZ((t<<4)|v)] = r[v];
    __syncthreads();
#pragma unroll
    for (int v=0;v<16;v++) r[v] = sh[SWZ((v<<8)|t)];
#pragma unroll
    for (int v=0;v<16;v++) buf[gbase0 | ((unsigned)v<<18)] = r[v];
  } else {
    // Fused final CNOT ladder + <Z_q> reduction.
    // Amp r[v] lives at g = (t<<14)|((v>>2)<<12)|(blk<<2)|(v&3) (mapping M2);
    // post-ladder basis label y_p = XOR of g bits p..21 (prefix-xor).
    float z[22];
#pragma unroll
    for (int q=0;q<22;q++) z[q] = 0.0f;
    float tot = 0.0f;
#pragma unroll
    for (int v=0;v<16;v++){
      unsigned g = ((unsigned)t<<14) | ((unsigned)(v>>2)<<12) | (blk<<2) | (unsigned)(v&3);
      unsigned y = g; y ^= y>>1; y ^= y>>2; y ^= y>>4; y ^= y>>8; y ^= y>>16;
      float re = __uint_as_float((unsigned)r[v]);
      float im = __uint_as_float((unsigned)(r[v]>>32));
      float p = re*re + im*im;
      tot += p;
#pragma unroll
      for (int q=0;q<22;q++)
        z[q] += ((y >> (21-q)) & 1u) ? -p : p;
    }
    __syncthreads();   // sacc initialized
#pragma unroll
    for (int q=0;q<22;q++){
      float val = z[q];
#pragma unroll
      for (int o=16;o;o>>=1) val += __shfl_down_sync(0xffffffffu, val, o);
      if ((t & 31) == 0) atomicAdd(&sacc[q], (double)val);
    }
    {
      float val = tot;
#pragma unroll
      for (int o=16;o;o>>=1) val += __shfl_down_sync(0xffffffffu, val, o);
      if ((t & 31) == 0) atomicAdd(&sacc[22], (double)val);
    }
    __syncthreads();
    if (t < 23) atomicAdd(&g_acc[t], sacc[t]);
  }
}

__global__ void k_final(float* __restrict__ out){
  int q = threadIdx.x;
  if (q < 22) out[q] = (float)(g_acc[q] / g_acc[22]);
}

extern "C" void kernel_launch(void* const* d_in, const int* in_sizes, int n_in,
                              void* d_out, int out_size)
{
  const float* params = (const float*)d_in[0];
  const float* sre    = (const float*)d_in[1];
  const float* sim    = (const float*)d_in[2];
  float* out = (float*)d_out;

  k_prep<<<1,128>>>(params);

  // Layer 1: A writes bufA (dir=1), B in-place on bufA (sel=1)
  k_passA<true ><<<1024,256>>>(sre, sim, 0, 1);
  k_passB<false><<<1024,256>>>(0, 1);
  // Layer 2: bufA -> bufB (dir=0), B on bufB (sel=0)
  k_passA<false><<<1024,256>>>(nullptr, nullptr, 1, 0);
  k_passB<false><<<1024,256>>>(1, 0);
  // Layer 3: bufB -> bufA
  k_passA<false><<<1024,256>>>(nullptr, nullptr, 2, 1);
  k_passB<false><<<1024,256>>>(2, 1);
  // Layer 4: bufA -> bufB, B fuses final ladder + reduction
  k_passA<false><<<1024,256>>>(nullptr, nullptr, 3, 0);
  k_passB<true ><<<1024,256>>>(3, 0);

  k_final<<<1,32>>>(out);
}

// round 3
// speedup vs baseline: 1.2065x; 1.2065x over previous
#include <cuda_runtime.h>

#define DIM (1u<<22)
typedef unsigned long long ull;

// Persistent scratch (allowed: __device__ globals, no allocation)
__device__ ull g_bufA[DIM];                 // packed (re,im) amplitudes
__device__ ull g_bufB[DIM];
__device__ __align__(16) ull g_Upk[4*22*8]; // per gate: 8 packed-broadcast consts
__device__ double g_acc[23];                // z[0..21], total at [22]

__device__ __forceinline__ int SWZ(int a){ return a ^ ((a>>4)&15); }

__device__ __forceinline__ ull fma2(ull a, ull b, ull c){
  ull d; asm("fma.rn.f32x2 %0, %1, %2, %3;" : "=l"(d) : "l"(a), "l"(b), "l"(c)); return d;
}
__device__ __forceinline__ ull mul2(ull a, ull b){
  ull d; asm("mul.rn.f32x2 %0, %1, %2;" : "=l"(d) : "l"(a), "l"(b)); return d;
}
__device__ __forceinline__ ull swp(ull a){ return (a>>32)|(a<<32); }
__device__ __forceinline__ ull packf(float lo, float hi){
  return (ull)__float_as_uint(lo) | ((ull)__float_as_uint(hi)<<32);
}

__device__ __forceinline__ float2 cxmul(float2 a, float2 b){
  return make_float2(a.x*b.x - a.y*b.y, a.x*b.y + a.y*b.x);
}

// Apply 2x2 gate on register-bit J over 16 register-resident packed amps.
// Complex update via packed f32x2: res = (u.x,u.x)*a + (-u.y,u.y)*swap(a) + ...
template<int J>
__device__ __forceinline__ void gate16(ull (&r)[16], const ull* __restrict__ Up){
  const ulonglong2 q0 = ((const ulonglong2*)Up)[0];
  const ulonglong2 q1 = ((const ulonglong2*)Up)[1];
  const ulonglong2 q2 = ((const ulonglong2*)Up)[2];
  const ulonglong2 q3 = ((const ulonglong2*)Up)[3];
  const ull c00=q0.x, d00=q0.y, c01=q1.x, d01=q1.y;
  const ull c10=q2.x, d10=q2.y, c11=q3.x, d11=q3.y;
#pragma unroll
  for (int i=0;i<16;i++){
    if ((i & (1<<J)) == 0){
      const int j2 = i | (1<<J);
      const ull a=r[i], b=r[j2], as=swp(a), bs=swp(b);
      r[i]  = fma2(c00,a, fma2(d00,as, fma2(c01,b, mul2(d01,bs))));
      r[j2] = fma2(c10,a, fma2(d10,as, fma2(c11,b, mul2(d11,bs))));
    }
  }
}

// ---------------------------------------------------------------------------
// Prep: zero accumulators, build 88 fused gates U = RZ*RY*RX, packed-broadcast
// ---------------------------------------------------------------------------
__global__ void k_prep(const float* __restrict__ params){
  int i = threadIdx.x;
  if (i < 23) g_acc[i] = 0.0;
  if (i < 88){
    float tx = 0.5f*params[i*3+0];
    float ty = 0.5f*params[i*3+1];
    float tz = 0.5f*params[i*3+2];
    float cx,sx,cy,sy,cz,sz;
    sincosf(tx,&sx,&cx); sincosf(ty,&sy,&cy); sincosf(tz,&sz,&cz);
    // M = RY*RX
    float2 M00 = make_float2( cy*cx,  sy*sx);
    float2 M01 = make_float2(-sy*cx, -cy*sx);
    float2 M10 = make_float2( sy*cx, -cy*sx);
    float2 M11 = make_float2( cy*cx, -sy*sx);
    float2 em = make_float2(cz,-sz), ep = make_float2(cz,sz); // e^{-itz}, e^{+itz}
    float2 U00=cxmul(em,M00), U01=cxmul(em,M01);
    float2 U10=cxmul(ep,M10), U11=cxmul(ep,M11);
    ull* Up = &g_Upk[i*8];
    Up[0]=packf(U00.x,U00.x); Up[1]=packf(-U00.y,U00.y);
    Up[2]=packf(U01.x,U01.x); Up[3]=packf(-U01.y,U01.y);
    Up[4]=packf(U10.x,U10.x); Up[5]=packf(-U10.y,U10.y);
    Up[6]=packf(U11.x,U11.x); Up[7]=packf(-U11.y,U11.y);
  }
}

// ---------------------------------------------------------------------------
// Pass A: gates on global bits 0..11 (qubits 21..10). Tile = 4096 contiguous.
// 256 thr x 16 amps; 3 staging mappings (4 reg bits each), swizzled LDS,
// minimal 3-barrier structure (write-back targets the just-read slots).
// Layers >= 2 fuse prior layer's CNOT ladder as Gray-code gather in[y^(y>>1)].
// ---------------------------------------------------------------------------
template<bool FIRST>
__global__ void __launch_bounds__(256,3) k_passA(
    const float* __restrict__ sre, const float* __restrict__ sim,
    int layer, int dir)
{
  __shared__ ull sh[4096];
  const int t = threadIdx.x;
  const unsigned base = (unsigned)blockIdx.x << 12;
  const ull* in  = dir ? g_bufB : g_bufA;
  ull*       out = dir ? g_bufA : g_bufB;
  const ull* Ub = &g_Upk[layer*22*8];
  ull r[16];

  if (FIRST){
#pragma unroll
    for (int v=0;v<16;v++){
      unsigned y = base | ((unsigned)v<<8) | (unsigned)t;
      r[v] = packf(sre[y], sim[y]);
    }
  } else {
#pragma unroll
    for (int v=0;v<16;v++){
      unsigned y = base | ((unsigned)v<<8) | (unsigned)t;
      unsigned x = y ^ (y>>1);          // inverse of CNOT-ladder permutation
      r[v] = in[x];
    }
  }
  // stage M0: reg bit j -> global bit 8+j -> qubit 13-j
  gate16<0>(r, Ub + 13*8);
  gate16<1>(r, Ub + 12*8);
  gate16<2>(r, Ub + 11*8);
  gate16<3>(r, Ub + 10*8);
  // exchange M0 -> M1
#pragma unroll
  for (int v=0;v<16;v++) sh[SWZ((v<<8)|t)] = r[v];
  __syncthreads();
#pragma unroll
  for (int v=0;v<16;v++) r[v] = sh[SWZ(((t>>4)<<8)|(v<<4)|(t&15))];
  // stage M1: reg bit j -> global bit 4+j -> qubit 17-j
  gate16<0>(r, Ub + 17*8);
  gate16<1>(r, Ub + 16*8);
  gate16<2>(r, Ub + 15*8);
  gate16<3>(r, Ub + 14*8);
  // exchange M1 -> M2 (write back to just-read slots: no pre-barrier needed)
#pragma unroll
  for (int v=0;v<16;v++) sh[SWZ(((t>>4)<<8)|(v<<4)|(t&15))] = r[v];
  __syncthreads();
#pragma unroll
  for (int v=0;v<16;v++) r[v] = sh[SWZ((t<<4)|v)];
  // stage M2: reg bit j -> global bit j -> qubit 21-j
  gate16<0>(r, Ub + 21*8);
  gate16<1>(r, Ub + 20*8);
  gate16<2>(r, Ub + 19*8);
  gate16<3>(r, Ub + 18*8);
  // exchange M2 -> M0 and coalesced store
#pragma unroll
  for (int v=0;v<16;v++) sh[SWZ((t<<4)|v)] = r[v];
  __syncthreads();
#pragma unroll
  for (int v=0;v<16;v++) r[v] = sh[SWZ((v<<8)|t)];
#pragma unroll
  for (int v=0;v<16;v++) out[base | ((unsigned)v<<8) | (unsigned)t] = r[v];
}

// ---------------------------------------------------------------------------
// Pass B: gates on global bits 12..21 (qubits 9..0). In-place.
// Tile local a (12b) = (c<<2)|v, c = bits 12..21, v = bits 0..1 payload.
// LAST fuses the final CNOT ladder + <Z_q> reduction (no final state store).
// ---------------------------------------------------------------------------
template<bool LAST>
__global__ void __launch_bounds__(256,3) k_passB(int layer, int sel)
{
  __shared__ ull sh[4096];
  __shared__ double sacc[23];
  const int t = threadIdx.x;
  const unsigned blk = blockIdx.x;
  ull* buf = sel ? g_bufA : g_bufB;
  const ull* Ub = &g_Upk[layer*22*8];
  ull r[16];

  if (LAST){
    if (t < 23) sacc[t] = 0.0;
  }

  // load, mapping M0: a=(v<<8)|t -> g = (v<<18)|((t>>2)<<12)|(blk<<2)|(t&3)
  const unsigned gbase0 = ((unsigned)(t>>2)<<12) | (blk<<2) | (unsigned)(t&3);
#pragma unroll
  for (int v=0;v<16;v++) r[v] = buf[gbase0 | ((unsigned)v<<18)];
  // stage M0: reg bit j -> global bit 18+j -> qubit 3-j
  gate16<0>(r, Ub + 3*8);
  gate16<1>(r, Ub + 2*8);
  gate16<2>(r, Ub + 1*8);
  gate16<3>(r, Ub + 0*8);
  // exchange M0 -> M1
#pragma unroll
  for (int v=0;v<16;v++) sh[SWZ((v<<8)|t)] = r[v];
  __syncthreads();
#pragma unroll
  for (int v=0;v<16;v++) r[v] = sh[SWZ(((t>>4)<<8)|(v<<4)|(t&15))];
  // stage M1: reg bit j -> global bit 14+j -> qubit 7-j
  gate16<0>(r, Ub + 7*8);
  gate16<1>(r, Ub + 6*8);
  gate16<2>(r, Ub + 5*8);
  gate16<3>(r, Ub + 4*8);
  // exchange M1 -> M2 (write back to just-read slots)
#pragma unroll
  for (int v=0;v<16;v++) sh[SWZ(((t>>4)<<8)|(v<<4)|(t&15))] = r[v];
  __syncthreads();
#pragma unroll
  for (int v=0;v<16;v++) r[v] = sh[SWZ((t<<4)|v)];
  // stage M2: reg bits 2,3 -> global bits 12,13 -> qubits 9,8
  gate16<2>(r, Ub + 9*8);
  gate16<3>(r, Ub + 8*8);

  if (!LAST){
    // exchange M2 -> M0 and in-place coalesced store
#pragma unroll
    for (int v=0;v<16;v++) sh[SWZ((t<<4)|v)] = r[v];
    __syncthreads();
#pragma unroll
    for (int v=0;v<16;v++) r[v] = sh[SWZ((v<<8)|t)];
#pragma unroll
    for (int v=0;v<16;v++) buf[gbase0 | ((unsigned)v<<18)] = r[v];
  } else {
    // Fused final CNOT ladder + <Z_q> reduction.
    // Amp r[v] lives at g = (t<<14)|((v>>2)<<12)|(blk<<2)|(v&3) (mapping M2);
    // post-ladder basis label y_p = XOR of g bits p..21 (prefix-xor).
    float z[22];
#pragma unroll
    for (int q=0;q<22;q++) z[q] = 0.0f;
    float tot = 0.0f;
#pragma unroll
    for (int v=0;v<16;v++){
      unsigned g = ((unsigned)t<<14) | ((unsigned)(v>>2)<<12) | (blk<<2) | (unsigned)(v&3);
      unsigned y = g; y ^= y>>1; y ^= y>>2; y ^= y>>4; y ^= y>>8; y ^= y>>16;
      float re = __uint_as_float((unsigned)r[v]);
      float im = __uint_as_float((unsigned)(r[v]>>32));
      float p = re*re + im*im;
      tot += p;
#pragma unroll
      for (int q=0;q<22;q++)
        z[q] += ((y >> (21-q)) & 1u) ? -p : p;
    }
    __syncthreads();   // sacc initialized
#pragma unroll
    for (int q=0;q<22;q++){
      float val = z[q];
#pragma unroll
      for (int o=16;o;o>>=1) val += __shfl_down_sync(0xffffffffu, val, o);
      if ((t & 31) == 0) atomicAdd(&sacc[q], (double)val);
    }
    {
      float val = tot;
#pragma unroll
      for (int o=16;o;o>>=1) val += __shfl_down_sync(0xffffffffu, val, o);
      if ((t & 31) == 0) atomicAdd(&sacc[22], (double)val);
    }
    __syncthreads();
    if (t < 23) atomicAdd(&g_acc[t], sacc[t]);
  }
}

__global__ void k_final(float* __restrict__ out){
  int q = threadIdx.x;
  if (q < 22) out[q] = (float)(g_acc[q] / g_acc[22]);
}

extern "C" void kernel_launch(void* const* d_in, const int* in_sizes, int n_in,
                              void* d_out, int out_size)
{
  const float* params = (const float*)d_in[0];
  const float* sre    = (const float*)d_in[1];
  const float* sim    = (const float*)d_in[2];
  float* out = (float*)d_out;

  k_prep<<<1,128>>>(params);

  // Layer 1: A writes bufA (dir=1), B in-place on bufA (sel=1)
  k_passA<true ><<<1024,256>>>(sre, sim, 0, 1);
  k_passB<false><<<1024,256>>>(0, 1);
  // Layer 2: bufA -> bufB (dir=0), B on bufB (sel=0)
  k_passA<false><<<1024,256>>>(nullptr, nullptr, 1, 0);
  k_passB<false><<<1024,256>>>(1, 0);
  // Layer 3: bufB -> bufA
  k_passA<false><<<1024,256>>>(nullptr, nullptr, 2, 1);
  k_passB<false><<<1024,256>>>(2, 1);
  // Layer 4: bufA -> bufB, B fuses final ladder + reduction
  k_passA<false><<<1024,256>>>(nullptr, nullptr, 3, 0);
  k_passB<true ><<<1024,256>>>(3, 0);

  k_final<<<1,32>>>(out);
}

// round 4
// speedup vs baseline: 1.5239x; 1.2631x over previous
#include <cuda_runtime.h>

#define DIM (1u<<22)
typedef unsigned long long ull;

// Persistent scratch (allowed: __device__ globals, no allocation)
__device__ ull g_bufA[DIM];                 // packed (re,im) amplitudes
__device__ ull g_bufB[DIM];
__device__ __align__(16) ull g_Upk[4*22*8]; // per gate: 8 packed-broadcast consts
__device__ double g_acc[23];                // z[0..21], total at [22]

__device__ __forceinline__ int SWZ(int a){ return a ^ ((a>>4)&15); }

__device__ __forceinline__ ull fma2(ull a, ull b, ull c){
  ull d; asm("fma.rn.f32x2 %0, %1, %2, %3;" : "=l"(d) : "l"(a), "l"(b), "l"(c)); return d;
}
__device__ __forceinline__ ull mul2(ull a, ull b){
  ull d; asm("mul.rn.f32x2 %0, %1, %2;" : "=l"(d) : "l"(a), "l"(b)); return d;
}
__device__ __forceinline__ ull swp(ull a){ return (a>>32)|(a<<32); }
__device__ __forceinline__ ull packf(float lo, float hi){
  return (ull)__float_as_uint(lo) | ((ull)__float_as_uint(hi)<<32);
}

__device__ __forceinline__ float2 cxmul(float2 a, float2 b){
  return make_float2(a.x*b.x - a.y*b.y, a.x*b.y + a.y*b.x);
}

// Apply 2x2 gate on register-bit J over 16 register-resident packed amps.
// Complex update via packed f32x2: res = (u.x,u.x)*a + (-u.y,u.y)*swap(a) + ...
template<int J>
__device__ __forceinline__ void gate16(ull (&r)[16], const ull* __restrict__ Up){
  const ulonglong2 q0 = ((const ulonglong2*)Up)[0];
  const ulonglong2 q1 = ((const ulonglong2*)Up)[1];
  const ulonglong2 q2 = ((const ulonglong2*)Up)[2];
  const ulonglong2 q3 = ((const ulonglong2*)Up)[3];
  const ull c00=q0.x, d00=q0.y, c01=q1.x, d01=q1.y;
  const ull c10=q2.x, d10=q2.y, c11=q3.x, d11=q3.y;
#pragma unroll
  for (int i=0;i<16;i++){
    if ((i & (1<<J)) == 0){
      const int j2 = i | (1<<J);
      const ull a=r[i], b=r[j2], as=swp(a), bs=swp(b);
      r[i]  = fma2(c00,a, fma2(d00,as, fma2(c01,b, mul2(d01,bs))));
      r[j2] = fma2(c10,a, fma2(d10,as, fma2(c11,b, mul2(d11,bs))));
    }
  }
}

// ---------------------------------------------------------------------------
// Prep: zero accumulators, build 88 fused gates U = RZ*RY*RX, packed-broadcast
// ---------------------------------------------------------------------------
__global__ void k_prep(const float* __restrict__ params){
  int i = threadIdx.x;
  if (i < 23) g_acc[i] = 0.0;
  if (i < 88){
    float tx = 0.5f*params[i*3+0];
    float ty = 0.5f*params[i*3+1];
    float tz = 0.5f*params[i*3+2];
    float cx,sx,cy,sy,cz,sz;
    sincosf(tx,&sx,&cx); sincosf(ty,&sy,&cy); sincosf(tz,&sz,&cz);
    // M = RY*RX
    float2 M00 = make_float2( cy*cx,  sy*sx);
    float2 M01 = make_float2(-sy*cx, -cy*sx);
    float2 M10 = make_float2( sy*cx, -cy*sx);
    float2 M11 = make_float2( cy*cx, -sy*sx);
    float2 em = make_float2(cz,-sz), ep = make_float2(cz,sz); // e^{-itz}, e^{+itz}
    float2 U00=cxmul(em,M00), U01=cxmul(em,M01);
    float2 U10=cxmul(ep,M10), U11=cxmul(ep,M11);
    ull* Up = &g_Upk[i*8];
    Up[0]=packf(U00.x,U00.x); Up[1]=packf(-U00.y,U00.y);
    Up[2]=packf(U01.x,U01.x); Up[3]=packf(-U01.y,U01.y);
    Up[4]=packf(U10.x,U10.x); Up[5]=packf(-U10.y,U10.y);
    Up[6]=packf(U11.x,U11.x); Up[7]=packf(-U11.y,U11.y);
  }
}

// ---------------------------------------------------------------------------
// Pass A: gates on global bits 0..11 (qubits 21..10). Tile = 4096 contiguous.
// 2-exchange structure: load in M1 (coalesced), stages M1 -> M2 -> M0,
// store in M0 (coalesced). Gate consts for stages 2-3 staged through smem.
// Layers >= 2 fuse prior layer's CNOT ladder as Gray-code gather in[y^(y>>1)].
//   M0: a=(v<<8)|t                  reg bits = a8..11
//   M1: a=((t>>4)<<8)|(v<<4)|(t&15) reg bits = a4..7
//   M2: a=(t<<4)|v                  reg bits = a0..3
// ---------------------------------------------------------------------------
template<bool FIRST>
__global__ void __launch_bounds__(256,3) k_passA(
    const float* __restrict__ sre, const float* __restrict__ sim,
    int layer, int dir)
{
  __shared__ ull sh[4096];
  __shared__ ull shU[64];               // stage M2 gates (q21..18), stage M0 gates (q13..10)
  const int t = threadIdx.x;
  const unsigned base = (unsigned)blockIdx.x << 12;
  const ull* in  = dir ? g_bufB : g_bufA;
  ull*       out = dir ? g_bufA : g_bufB;
  const ull* Ub = &g_Upk[layer*22*8];
  ull r[16];

  if (t < 64){
    const int qmap[8] = {21,20,19,18, 13,12,11,10};
    shU[t] = Ub[qmap[t>>3]*8 + (t&7)];
  }

  // load in mapping M1: a = ((t>>4)<<8)|(v<<4)|(t&15)
  const unsigned aM1b = (((unsigned)t>>4)<<8) | ((unsigned)t&15);
  if (FIRST){
#pragma unroll
    for (int v=0;v<16;v++){
      unsigned y = base | aM1b | ((unsigned)v<<4);
      r[v] = packf(sre[y], sim[y]);
    }
  } else {
#pragma unroll
    for (int v=0;v<16;v++){
      unsigned y = base | aM1b | ((unsigned)v<<4);
      unsigned x = y ^ (y>>1);          // inverse of CNOT-ladder permutation
      r[v] = in[x];
    }
  }
  // stage M1: reg bit j -> a bit 4+j -> qubit 17-j
  gate16<0>(r, Ub + 17*8);
  gate16<1>(r, Ub + 16*8);
  gate16<2>(r, Ub + 15*8);
  gate16<3>(r, Ub + 14*8);
  // exchange M1 -> M2
#pragma unroll
  for (int v=0;v<16;v++) sh[SWZ(aM1b | (v<<4))] = r[v];
  __syncthreads();
#pragma unroll
  for (int v=0;v<16;v++) r[v] = sh[SWZ((t<<4)|v)];
  // stage M2: reg bit j -> a bit j -> qubit 21-j (consts from smem)
  gate16<0>(r, shU + 0);
  gate16<1>(r, shU + 8);
  gate16<2>(r, shU + 16);
  gate16<3>(r, shU + 24);
  // exchange M2 -> M0 (write back to just-read slots: no pre-barrier needed)
#pragma unroll
  for (int v=0;v<16;v++) sh[SWZ((t<<4)|v)] = r[v];
  __syncthreads();
#pragma unroll
  for (int v=0;v<16;v++) r[v] = sh[SWZ((v<<8)|t)];
  // stage M0: reg bit j -> a bit 8+j -> qubit 13-j (consts from smem)
  gate16<0>(r, shU + 32);
  gate16<1>(r, shU + 40);
  gate16<2>(r, shU + 48);
  gate16<3>(r, shU + 56);
  // store in M0: coalesced
#pragma unroll
  for (int v=0;v<16;v++) out[base | ((unsigned)v<<8) | (unsigned)t] = r[v];
}

// ---------------------------------------------------------------------------
// Pass B: gates on global bits 12..21 (qubits 9..0). In-place.
// Tile local a (12b): a bits 0..1 = global bits 0..1 (payload),
// a bit k (k>=2) = global bit 10+k.  g = ((a>>2)<<12)|(blk<<2)|(a&3).
// 2-exchange structure: load M1, stages M1 -> M2 -> M0, store M0.
// LAST fuses the final CNOT ladder + <Z_q> reduction (no final state store).
// ---------------------------------------------------------------------------
template<bool LAST>
__global__ void __launch_bounds__(256,3) k_passB(int layer, int sel)
{
  __shared__ ull sh[4096];
  __shared__ ull shU[48];               // stage M2 gates (q9,q8), stage M0 gates (q3..0)
  __shared__ double sacc[23];
  const int t = threadIdx.x;
  const unsigned blk = blockIdx.x;
  ull* buf = sel ? g_bufA : g_bufB;
  const ull* Ub = &g_Upk[layer*22*8];
  ull r[16];

  if (t < 48){
    const int qmap[6] = {9,8, 3,2,1,0};
    shU[t] = Ub[qmap[t>>3]*8 + (t&7)];
  }
  if (LAST){
    if (t >= 64 && t < 87) sacc[t-64] = 0.0;
  }

  // load in mapping M1: a = ((t>>4)<<8)|(v<<4)|(t&15)
  //   g = ((a>>2)<<12) | (blk<<2) | (a&3)
  const unsigned aM1b = (((unsigned)t>>4)<<8) | ((unsigned)t&15);
#pragma unroll
  for (int v=0;v<16;v++){
    unsigned a = aM1b | ((unsigned)v<<4);
    unsigned g = ((a>>2)<<12) | (blk<<2) | (a&3);
    r[v] = buf[g];
  }
  // stage M1: reg bit j -> a bit 4+j -> global bit 14+j -> qubit 7-j
  gate16<0>(r, Ub + 7*8);
  gate16<1>(r, Ub + 6*8);
  gate16<2>(r, Ub + 5*8);
  gate16<3>(r, Ub + 4*8);
  // exchange M1 -> M2
#pragma unroll
  for (int v=0;v<16;v++) sh[SWZ(aM1b | (v<<4))] = r[v];
  __syncthreads();
#pragma unroll
  for (int v=0;v<16;v++) r[v] = sh[SWZ((t<<4)|v)];
  // stage M2: reg bits 2,3 -> a bits 2,3 -> global 12,13 -> qubits 9,8
  gate16<2>(r, shU + 0);
  gate16<3>(r, shU + 8);
  // exchange M2 -> M0 (write back to just-read slots)
#pragma unroll
  for (int v=0;v<16;v++) sh[SWZ((t<<4)|v)] = r[v];
  __syncthreads();
#pragma unroll
  for (int v=0;v<16;v++) r[v] = sh[SWZ((v<<8)|t)];
  // stage M0: reg bit j -> a bit 8+j -> global bit 18+j -> qubit 3-j
  gate16<0>(r, shU + 16);
  gate16<1>(r, shU + 24);
  gate16<2>(r, shU + 32);
  gate16<3>(r, shU + 40);

  // M0 global address: a=(v<<8)|t -> g = (v<<18)|((t>>2)<<12)|(blk<<2)|(t&3)
  const unsigned gbase0 = (((unsigned)t>>2)<<12) | (blk<<2) | ((unsigned)t&3);
  if (!LAST){
#pragma unroll
    for (int v=0;v<16;v++) buf[gbase0 | ((unsigned)v<<18)] = r[v];
  } else {
    // Fused final CNOT ladder + <Z_q> reduction.
    // r[v] lives at g; post-ladder basis label y_p = XOR of g bits p..21.
    float z[22];
#pragma unroll
    for (int q=0;q<22;q++) z[q] = 0.0f;
    float tot = 0.0f;
#pragma unroll
    for (int v=0;v<16;v++){
      unsigned g = gbase0 | ((unsigned)v<<18);
      unsigned y = g; y ^= y>>1; y ^= y>>2; y ^= y>>4; y ^= y>>8; y ^= y>>16;
      float re = __uint_as_float((unsigned)r[v]);
      float im = __uint_as_float((unsigned)(r[v]>>32));
      float p = re*re + im*im;
      tot += p;
#pragma unroll
      for (int q=0;q<22;q++)
        z[q] += ((y >> (21-q)) & 1u) ? -p : p;
    }
    __syncthreads();   // sacc initialized (done before the mainloop barriers anyway)
#pragma unroll
    for (int q=0;q<22;q++){
      float val = z[q];
#pragma unroll
      for (int o=16;o;o>>=1) val += __shfl_down_sync(0xffffffffu, val, o);
      if ((t & 31) == 0) atomicAdd(&sacc[q], (double)val);
    }
    {
      float val = tot;
#pragma unroll
      for (int o=16;o;o>>=1) val += __shfl_down_sync(0xffffffffu, val, o);
      if ((t & 31) == 0) atomicAdd(&sacc[22], (double)val);
    }
    __syncthreads();
    if (t < 23) atomicAdd(&g_acc[t], sacc[t]);
  }
}

__global__ void k_final(float* __restrict__ out){
  int q = threadIdx.x;
  if (q < 22) out[q] = (float)(g_acc[q] / g_acc[22]);
}

extern "C" void kernel_launch(void* const* d_in, const int* in_sizes, int n_in,
                              void* d_out, int out_size)
{
  const float* params = (const float*)d_in[0];
  const float* sre    = (const float*)d_in[1];
  const float* sim    = (const float*)d_in[2];
  float* out = (float*)d_out;

  k_prep<<<1,128>>>(params);

  // Layer 1: A writes bufA (dir=1), B in-place on bufA (sel=1)
  k_passA<true ><<<1024,256>>>(sre, sim, 0, 1);
  k_passB<false><<<1024,256>>>(0, 1);
  // Layer 2: bufA -> bufB (dir=0), B on bufB (sel=0)
  k_passA<false><<<1024,256>>>(nullptr, nullptr, 1, 0);
  k_passB<false><<<1024,256>>>(1, 0);
  // Layer 3: bufB -> bufA
  k_passA<false><<<1024,256>>>(nullptr, nullptr, 2, 1);
  k_passB<false><<<1024,256>>>(2, 1);
  // Layer 4: bufA -> bufB, B fuses final ladder + reduction
  k_passA<false><<<1024,256>>>(nullptr, nullptr, 3, 0);
  k_passB<true ><<<1024,256>>>(3, 0);

  k_final<<<1,32>>>(out);
}